// round 7
// baseline (speedup 1.0000x reference)
#include <cuda_runtime.h>
#include <cuda_bf16.h>
#include <cstdint>

// Problem dims (fixed by the dataset)
#define N_   64
#define C_   64
#define T_   300
#define V_   25
#define S_   3
#define TT   4              // t positions per block
#define COLS 100            // TT*V_
#define TBLK 75             // T_/TT
#define NTHREADS 256

// -------- global folded parameters (written by prep kernel) --------
__device__ __align__(16) uint4 g_Wf[S_ * 4 * 8 * 32];   // W frags [s][kt][ntg][lane]
__device__ __align__(16) uint4 g_Af[S_ * 2 * 2 * 2 * 32]; // Ae^T frags [s][mt][kt][hl][lane]
__device__ __align__(16) float g_ab[128];                // alpha | bshift

// ---------------- bf16 / mma helpers ----------------
// packbf(hi_elem, lo_elem): low 16 bits = bf16(lo_elem)
__device__ __forceinline__ uint32_t packbf(float hi, float lo) {
    uint32_t d;
    asm("cvt.rn.bf16x2.f32 %0, %1, %2;" : "=r"(d) : "f"(hi), "f"(lo));
    return d;
}
__device__ __forceinline__ void mma16816(float* c, const uint32_t* a,
                                         uint32_t b0, uint32_t b1) {
    asm volatile(
        "mma.sync.aligned.m16n8k16.row.col.f32.bf16.bf16.f32 "
        "{%0,%1,%2,%3}, {%4,%5,%6,%7}, {%8,%9}, {%0,%1,%2,%3};"
        : "+f"(c[0]), "+f"(c[1]), "+f"(c[2]), "+f"(c[3])
        : "r"(a[0]), "r"(a[1]), "r"(a[2]), "r"(a[3]), "r"(b0), "r"(b1));
}

// ---------------- prep: fold params (tiny, few blocks) ----------------
__global__ void unit_gcn_prep(const float* __restrict__ pA,
                              const float* __restrict__ pPA1,
                              const float* __restrict__ pPA2,
                              const float* __restrict__ pWc,
                              const float* __restrict__ pbc,
                              const float* __restrict__ pgamma,
                              const float* __restrict__ pbeta,
                              const float* __restrict__ prmean,
                              const float* __restrict__ prvar) {
    int tid = blockIdx.x * blockDim.x + threadIdx.x;

    // W fragments for GEMM2 B operand (col-major KxN), hi/lo bf16.
    for (int i = tid; i < S_ * 4 * 8 * 32; i += blockDim.x * gridDim.x) {
        int lane = i & 31;
        int ntg  = (i >> 5) & 7;
        int kt   = (i >> 8) & 3;
        int s    = i >> 10;
        int n  = ntg * 8 + (lane >> 2);
        int k0 = kt * 16 + (lane & 3) * 2;
        const float* wr = pWc + (s * 64 + n) * 64;
        float w0 = wr[k0], w1 = wr[k0 + 1], w8 = wr[k0 + 8], w9 = wr[k0 + 9];
        uint32_t h01 = packbf(w1, w0);
        uint32_t h89 = packbf(w9, w8);
        float r0 = w0 - __uint_as_float(h01 << 16);
        float r1 = w1 - __uint_as_float(h01 & 0xffff0000u);
        float r8 = w8 - __uint_as_float(h89 << 16);
        float r9 = w9 - __uint_as_float(h89 & 0xffff0000u);
        uint4 frag;
        frag.x = h01;
        frag.y = h89;
        frag.z = packbf(r1, r0);
        frag.w = packbf(r9, r8);
        g_Wf[i] = frag;
    }

    // Ae^T fragments for GEMM1 A operand (row-major 32x32, m=w, k=v), hi/lo.
    for (int i = tid; i < S_ * 2 * 2 * 2 * 32; i += blockDim.x * gridDim.x) {
        int lane = i & 31;
        int hl = (i >> 5) & 1;
        int kt = (i >> 6) & 1;
        int mt = (i >> 7) & 1;
        int s  = i >> 8;
        int gm = mt * 16 + (lane >> 2);
        int k0 = kt * 16 + (lane & 3) * 2;
        float e[8];
        int ms[2] = {gm, gm + 8};
        int ks[4] = {k0, k0 + 1, k0 + 8, k0 + 9};
#pragma unroll
        for (int kk = 0; kk < 4; kk++)
#pragma unroll
            for (int mm = 0; mm < 2; mm++) {
                int m = ms[mm], k = ks[kk];
                float v = 0.0f;
                if (m < V_ && k < V_) {
                    int idx = (s * V_ + k) * V_ + m;
                    v = pA[idx] * pPA1[idx] + pPA2[idx];
                }
                e[kk * 2 + mm] = v;
            }
        if (hl) {
#pragma unroll
            for (int q = 0; q < 8; q++) {
                float h = __bfloat162float(__float2bfloat16(e[q]));
                e[q] = e[q] - h;
            }
        }
        uint4 frag;
        frag.x = packbf(e[2], e[0]);
        frag.y = packbf(e[3], e[1]);
        frag.z = packbf(e[6], e[4]);
        frag.w = packbf(e[7], e[5]);
        g_Af[i] = frag;
    }

    // BN fold: out = gemm*alpha + bshift (+x, relu). Bias folded into bshift.
    if (tid < C_) {
        float sc = pgamma[tid] / sqrtf(prvar[tid] + 1e-5f);
        float btot = pbc[tid] + pbc[64 + tid] + pbc[128 + tid];
        g_ab[tid] = sc;
        g_ab[64 + tid] = btot * sc + (pbeta[tid] - prmean[tid] * sc);
    }
}

// ---------------- main fused kernel ----------------
// smem layout (floats)
#define AB_O   0                      // 128: alpha|bshift
#define A2H_O  128                    // 32 x 136 = 4352 (GEMM2 A hi, bf16x2 words)
#define A2L_O  4480                   // 4352 (lo)
#define XBH_O  8832                   // 16 x 264 = 4224 (GEMM1 B hi)
#define XBL_O  13056                  // 4224 (lo)
#define XS_O   17280                  // 64*4*27 = 6912 (fp32 residual)
#define SMEM_FLOATS 24192
#define SMEM_BYTES  (SMEM_FLOATS * 4) // 96768 -> 2 CTAs/SM

__global__ void __launch_bounds__(NTHREADS, 2)
unit_gcn_main(const float* __restrict__ x, float* __restrict__ out) {
    const int n  = blockIdx.y;
    const int bx = blockIdx.x;       // t-tile
    const int t0 = bx * TT;
    const int tid = threadIdx.x;
    const int wid = tid >> 5;
    const int lane = tid & 31;

    extern __shared__ float sm[];
    float* ab = sm + AB_O;
    uint32_t* a2h = (uint32_t*)(sm + A2H_O);
    uint32_t* a2l = (uint32_t*)(sm + A2L_O);
    uint32_t* xbh = (uint32_t*)(sm + XBH_O);
    uint32_t* xbl = (uint32_t*)(sm + XBL_O);
    float* xs = sm + XS_O;

    // Stage BN constants
    if (tid < 128) ab[tid] = g_ab[tid];

    // Zero xb pad rows 12..15 (v >= 25 region; v=24 data lands in row 12 half 0)
    for (int i = tid; i < 4 * 264; i += NTHREADS) {
        xbh[12 * 264 + i] = 0u;
        xbl[12 * 264 + i] = 0u;
    }
    __syncthreads();   // pad-zero must precede staging writes into row 12

    // Stage x tile: fp32 residual copy + k-packed bf16 hi/lo for GEMM1 B.
    {
        const float4* xp = (const float4*)x;
        __nv_bfloat16* bh = (__nv_bfloat16*)xbh;
        __nv_bfloat16* bl = (__nv_bfloat16*)xbl;
        for (int q = tid; q < 1600; q += NTHREADS) {
            int c = q / 25;
            int f = q % 25;
            float4 val = xp[(n * 64 + c) * 1875 + bx * 25 + f];
            int p0 = f * 4;
            float vv[4] = {val.x, val.y, val.z, val.w};
#pragma unroll
            for (int j = 0; j < 4; j++) {
                int p = p0 + j;
                int tt = p / 25;
                int w = p - tt * 25;        // joint index v
                float v = vv[j];
                xs[(c * 4 + tt) * 27 + w] = v;
                __nv_bfloat16 h = __float2bfloat16(v);
                __nv_bfloat16 l = __float2bfloat16(v - __bfloat162float(h));
                int half = ((w >> 1) * 264 + tt * 64 + c) * 2 + (w & 1);
                bh[half] = h;
                bl[half] = l;
            }
        }
    }
    __syncthreads();

    // GEMM2 warp coords: warp wid owns m rows [wid*16, wid*16+16), ALL 64 n.
    // Warp 7 (rows 112..127) is past COLS -> skips GEMM2 + epilogue.
    const bool live = (wid < 7);

    float acc[8][4];
#pragma unroll
    for (int j = 0; j < 8; j++)
#pragma unroll
        for (int q = 0; q < 4; q++) acc[j][q] = 0.0f;

#pragma unroll
    for (int s = 0; s < S_; s++) {
        // ======== GEMM1: D1[w, tt*64+c] = Ae^T . xs  (M=32,N=256,K=32) ========
        // warp owns n-slice [wid*32, wid*32+32)
        {
            uint4 AH[2][2], AL[2][2];
#pragma unroll
            for (int mt = 0; mt < 2; mt++)
#pragma unroll
                for (int kt = 0; kt < 2; kt++) {
                    AH[mt][kt] = __ldg(g_Af + ((((s * 2 + mt) * 2 + kt) * 2 + 0) * 32) + lane);
                    AL[mt][kt] = __ldg(g_Af + ((((s * 2 + mt) * 2 + kt) * 2 + 1) * 32) + lane);
                }

            float d1[2][4][4];
#pragma unroll
            for (int i = 0; i < 2; i++)
#pragma unroll
                for (int j = 0; j < 4; j++)
#pragma unroll
                    for (int q = 0; q < 4; q++) d1[i][j][q] = 0.0f;

#pragma unroll
            for (int kt = 0; kt < 2; kt++) {
                const int rb = kt * 8 + (lane & 3);
#pragma unroll
                for (int nt = 0; nt < 4; nt++) {
                    const int nn = wid * 32 + nt * 8 + (lane >> 2);
                    uint32_t bh0 = xbh[rb * 264 + nn];
                    uint32_t bh1 = xbh[(rb + 4) * 264 + nn];
                    uint32_t bl0 = xbl[rb * 264 + nn];
                    uint32_t bl1 = xbl[(rb + 4) * 264 + nn];
#pragma unroll
                    for (int mt = 0; mt < 2; mt++) {
                        mma16816(d1[mt][nt], (const uint32_t*)&AH[mt][kt], bh0, bh1);
                        mma16816(d1[mt][nt], (const uint32_t*)&AL[mt][kt], bh0, bh1);
                        mma16816(d1[mt][nt], (const uint32_t*)&AH[mt][kt], bl0, bl1);
                    }
                }
            }

            // ---- pack D1 pairs (adjacent channels) into GEMM2 A layout ----
#pragma unroll
            for (int nt = 0; nt < 4; nt++) {
                const int n0 = wid * 32 + nt * 8 + (lane & 3) * 2;
                const int cw = (n0 & 63) >> 1;     // channel pair = A2 row
                const int tt = n0 >> 6;
#pragma unroll
                for (int mt = 0; mt < 2; mt++) {
                    const int gm = mt * 16 + (lane >> 2);
                    const float* dd = d1[mt][nt];
                    if (gm < V_) {
                        int m2 = tt * 25 + gm;
                        uint32_t h = packbf(dd[1], dd[0]);
                        float r0 = dd[0] - __uint_as_float(h << 16);
                        float r1 = dd[1] - __uint_as_float(h & 0xffff0000u);
                        a2h[cw * 136 + m2] = h;
                        a2l[cw * 136 + m2] = packbf(r1, r0);
                    }
                    if (gm + 8 < V_) {
                        int m2 = tt * 25 + gm + 8;
                        uint32_t h = packbf(dd[3], dd[2]);
                        float r0 = dd[2] - __uint_as_float(h << 16);
                        float r1 = dd[3] - __uint_as_float(h & 0xffff0000u);
                        a2h[cw * 136 + m2] = h;
                        a2l[cw * 136 + m2] = packbf(r1, r0);
                    }
                }
            }
        }
        __syncthreads();   // A2 tiles ready

        // ======== GEMM2: acc[m][o] += xa^T . W  (M=128,N=64,K=64), 8x1 layout ====
        if (live) {
            const uint4* wfs = g_Wf + (s * 4) * 8 * 32 + lane;
            const int m = wid * 16 + (lane >> 2);
#pragma unroll
            for (int kt = 0; kt < 4; kt++) {
                const int kr = kt * 8 + (lane & 3);
                uint32_t ah[4], al[4];
                ah[0] = a2h[kr * 136 + m];
                ah[1] = a2h[kr * 136 + m + 8];
                ah[2] = a2h[(kr + 4) * 136 + m];
                ah[3] = a2h[(kr + 4) * 136 + m + 8];
                al[0] = a2l[kr * 136 + m];
                al[1] = a2l[kr * 136 + m + 8];
                al[2] = a2l[(kr + 4) * 136 + m];
                al[3] = a2l[(kr + 4) * 136 + m + 8];
#pragma unroll
                for (int j = 0; j < 8; j++) {
                    uint4 Bf = __ldg(wfs + (kt * 8 + j) * 32);
                    mma16816(acc[j], ah, Bf.x, Bf.y);
                    mma16816(acc[j], al, Bf.x, Bf.y);
                    mma16816(acc[j], ah, Bf.z, Bf.w);
                }
            }
        }
        if (s < S_ - 1) __syncthreads();   // before next s overwrites A2
    }

    // -------- Epilogue: BN + residual + relu, store --------
    if (live) {
#pragma unroll
        for (int half = 0; half < 2; half++) {
            int m = wid * 16 + (lane >> 2) + half * 8;
            if (m < COLS) {
                int tt = m / 25;
                int w  = m - tt * 25;
                int base = n * 480000 + (t0 + tt) * 25 + w;
                const float* xsr = xs + tt * 27 + w;
#pragma unroll
                for (int j = 0; j < 8; j++) {
                    int o0 = j * 8 + (lane & 3) * 2;
                    float2 Al = *(const float2*)(ab + o0);
                    float2 Bs = *(const float2*)(ab + 64 + o0);
                    float c0 = acc[j][half * 2];
                    float c1 = acc[j][half * 2 + 1];
                    float r0 = xsr[o0 * 108];          // xs[(o0*4+tt)*27+w]
                    float r1 = xsr[(o0 + 1) * 108];
                    float y0 = fmaf(c0, Al.x, Bs.x) + r0;
                    float y1 = fmaf(c1, Al.y, Bs.y) + r1;
                    out[base + o0 * 7500]       = fmaxf(y0, 0.0f);
                    out[base + (o0 + 1) * 7500] = fmaxf(y1, 0.0f);
                }
            }
        }
    }
}

extern "C" void kernel_launch(void* const* d_in, const int* in_sizes, int n_in,
                              void* d_out, int out_size) {
    const float* x     = (const float*)d_in[0];
    const float* A     = (const float*)d_in[1];
    const float* PA1   = (const float*)d_in[2];
    const float* PA2   = (const float*)d_in[3];
    const float* Wc    = (const float*)d_in[4];
    const float* bc    = (const float*)d_in[5];
    const float* gamma = (const float*)d_in[6];
    const float* beta  = (const float*)d_in[7];
    const float* rmean = (const float*)d_in[8];
    const float* rvar  = (const float*)d_in[9];
    float* out = (float*)d_out;

    unit_gcn_prep<<<8, 256>>>(A, PA1, PA2, Wc, bc, gamma, beta, rmean, rvar);

    cudaFuncSetAttribute(unit_gcn_main,
                         cudaFuncAttributeMaxDynamicSharedMemorySize, SMEM_BYTES);
    dim3 grid(TBLK, N_);
    unit_gcn_main<<<grid, NTHREADS, SMEM_BYTES>>>(x, out);
}

// round 8
// speedup vs baseline: 1.1535x; 1.1535x over previous
#include <cuda_runtime.h>
#include <cuda_bf16.h>
#include <cstdint>

// Problem dims (fixed by the dataset)
#define N_   64
#define C_   64
#define T_   300
#define V_   25
#define S_   3
#define TT   4              // t positions per block
#define COLS 100            // TT*V_
#define TBLK 75             // T_/TT
#define NTHREADS 256

// -------- global folded parameters (written by prep kernel) --------
__device__ __align__(16) uint4 g_Wf[S_ * 4 * 8 * 32];   // W frags [s][kt][ntg][lane]
__device__ __align__(16) uint4 g_Af[S_ * 2 * 2 * 2 * 32]; // Ae^T frags [s][mt][kt][hl][lane]
__device__ __align__(16) float g_ab[128];                // alpha | bshift

// ---------------- bf16 / mma helpers ----------------
// packbf(hi_elem, lo_elem): low 16 bits = bf16(lo_elem)
__device__ __forceinline__ uint32_t packbf(float hi, float lo) {
    uint32_t d;
    asm("cvt.rn.bf16x2.f32 %0, %1, %2;" : "=r"(d) : "f"(hi), "f"(lo));
    return d;
}
__device__ __forceinline__ void mma16816(float* c, const uint32_t* a,
                                         uint32_t b0, uint32_t b1) {
    asm volatile(
        "mma.sync.aligned.m16n8k16.row.col.f32.bf16.bf16.f32 "
        "{%0,%1,%2,%3}, {%4,%5,%6,%7}, {%8,%9}, {%0,%1,%2,%3};"
        : "+f"(c[0]), "+f"(c[1]), "+f"(c[2]), "+f"(c[3])
        : "r"(a[0]), "r"(a[1]), "r"(a[2]), "r"(a[3]), "r"(b0), "r"(b1));
}
__device__ __forceinline__ void ldsm_x4(uint32_t* r, uint32_t addr) {
    asm volatile(
        "ldmatrix.sync.aligned.m8n8.x4.shared.b16 {%0,%1,%2,%3}, [%4];"
        : "=r"(r[0]), "=r"(r[1]), "=r"(r[2]), "=r"(r[3]) : "r"(addr));
}
__device__ __forceinline__ uint32_t smem_u32_of(const void* p) {
    uint32_t a;
    asm("{ .reg .u64 t; cvta.to.shared.u64 t, %1; cvt.u32.u64 %0, t; }"
        : "=r"(a) : "l"(p));
    return a;
}

// ---------------- prep: fold params (tiny, few blocks) ----------------
__global__ void unit_gcn_prep(const float* __restrict__ pA,
                              const float* __restrict__ pPA1,
                              const float* __restrict__ pPA2,
                              const float* __restrict__ pWc,
                              const float* __restrict__ pbc,
                              const float* __restrict__ pgamma,
                              const float* __restrict__ pbeta,
                              const float* __restrict__ prmean,
                              const float* __restrict__ prvar) {
    int tid = blockIdx.x * blockDim.x + threadIdx.x;

    // W fragments for GEMM2 B operand (col-major KxN), hi/lo bf16.
    for (int i = tid; i < S_ * 4 * 8 * 32; i += blockDim.x * gridDim.x) {
        int lane = i & 31;
        int ntg  = (i >> 5) & 7;
        int kt   = (i >> 8) & 3;
        int s    = i >> 10;
        int n  = ntg * 8 + (lane >> 2);
        int k0 = kt * 16 + (lane & 3) * 2;
        const float* wr = pWc + (s * 64 + n) * 64;
        float w0 = wr[k0], w1 = wr[k0 + 1], w8 = wr[k0 + 8], w9 = wr[k0 + 9];
        uint32_t h01 = packbf(w1, w0);
        uint32_t h89 = packbf(w9, w8);
        float r0 = w0 - __uint_as_float(h01 << 16);
        float r1 = w1 - __uint_as_float(h01 & 0xffff0000u);
        float r8 = w8 - __uint_as_float(h89 << 16);
        float r9 = w9 - __uint_as_float(h89 & 0xffff0000u);
        uint4 frag;
        frag.x = h01;
        frag.y = h89;
        frag.z = packbf(r1, r0);
        frag.w = packbf(r9, r8);
        g_Wf[i] = frag;
    }

    // Ae^T fragments for GEMM1 A operand (row-major 32x32, m=w, k=v), hi/lo.
    for (int i = tid; i < S_ * 2 * 2 * 2 * 32; i += blockDim.x * gridDim.x) {
        int lane = i & 31;
        int hl = (i >> 5) & 1;
        int kt = (i >> 6) & 1;
        int mt = (i >> 7) & 1;
        int s  = i >> 8;
        int gm = mt * 16 + (lane >> 2);
        int k0 = kt * 16 + (lane & 3) * 2;
        float e[8];
        int ms[2] = {gm, gm + 8};
        int ks[4] = {k0, k0 + 1, k0 + 8, k0 + 9};
#pragma unroll
        for (int kk = 0; kk < 4; kk++)
#pragma unroll
            for (int mm = 0; mm < 2; mm++) {
                int m = ms[mm], k = ks[kk];
                float v = 0.0f;
                if (m < V_ && k < V_) {
                    int idx = (s * V_ + k) * V_ + m;
                    v = pA[idx] * pPA1[idx] + pPA2[idx];
                }
                e[kk * 2 + mm] = v;
            }
        if (hl) {
#pragma unroll
            for (int q = 0; q < 8; q++) {
                float h = __bfloat162float(__float2bfloat16(e[q]));
                e[q] = e[q] - h;
            }
        }
        uint4 frag;
        frag.x = packbf(e[2], e[0]);
        frag.y = packbf(e[3], e[1]);
        frag.z = packbf(e[6], e[4]);
        frag.w = packbf(e[7], e[5]);
        g_Af[i] = frag;
    }

    // BN fold: out = gemm*alpha + bshift (+x, relu). Bias folded into bshift.
    if (tid < C_) {
        float sc = pgamma[tid] / sqrtf(prvar[tid] + 1e-5f);
        float btot = pbc[tid] + pbc[64 + tid] + pbc[128 + tid];
        g_ab[tid] = sc;
        g_ab[64 + tid] = btot * sc + (pbeta[tid] - prmean[tid] * sc);
    }
}

// ---------------- main fused kernel ----------------
// smem layout (float index). A2 layout: [m][kw], 36-word rows (144B) for
// conflict-free ldmatrix (phase banks 4m+c cover all 32) and pack-stores.
#define AB_O   0                      // 128: alpha|bshift
#define A2H_O  128                    // 112 x 36 = 4032 (GEMM2 A hi, bf16x2 words)
#define A2L_O  4160                   // 4032 (lo)
#define XBH_O  8192                   // 16 x 264 = 4224 (GEMM1 B hi)
#define XBL_O  12416                  // 4224 (lo)
#define SMEM_FLOATS 16640
#define SMEM_BYTES  (SMEM_FLOATS * 4) // 66560 -> 2 CTAs/SM (regs limit)

__global__ void __launch_bounds__(NTHREADS, 2)
unit_gcn_main(const float* __restrict__ x, float* __restrict__ out) {
    const int n  = blockIdx.y;
    const int bx = blockIdx.x;       // t-tile
    const int t0 = bx * TT;
    const int tid = threadIdx.x;
    const int wid = tid >> 5;
    const int lane = tid & 31;

    extern __shared__ float sm[];
    float* ab = sm + AB_O;
    uint32_t* a2h = (uint32_t*)(sm + A2H_O);
    uint32_t* a2l = (uint32_t*)(sm + A2L_O);
    uint32_t* xbh = (uint32_t*)(sm + XBH_O);
    uint32_t* xbl = (uint32_t*)(sm + XBL_O);

    // Stage BN constants
    if (tid < 128) ab[tid] = g_ab[tid];

    // Zero xb pad rows 12..15 (v >= 25 region; v=24 lands in row 12 half 0)
    for (int i = tid; i < 4 * 264; i += NTHREADS) {
        xbh[12 * 264 + i] = 0u;
        xbl[12 * 264 + i] = 0u;
    }
    __syncthreads();   // pad-zero must precede staging writes into row 12

    // Stage x tile as k-packed bf16 hi/lo for GEMM1 B.
    {
        const float4* xp = (const float4*)x;
        __nv_bfloat16* bh = (__nv_bfloat16*)xbh;
        __nv_bfloat16* bl = (__nv_bfloat16*)xbl;
        for (int q = tid; q < 1600; q += NTHREADS) {
            int c = q / 25;
            int f = q % 25;
            float4 val = xp[(n * 64 + c) * 1875 + bx * 25 + f];
            int p0 = f * 4;
            float vv[4] = {val.x, val.y, val.z, val.w};
#pragma unroll
            for (int j = 0; j < 4; j++) {
                int p = p0 + j;
                int tt = p / 25;
                int w = p - tt * 25;        // joint index v
                float v = vv[j];
                __nv_bfloat16 h = __float2bfloat16(v);
                __nv_bfloat16 l = __float2bfloat16(v - __bfloat162float(h));
                int half = ((w >> 1) * 264 + tt * 64 + c) * 2 + (w & 1);
                bh[half] = h;
                bl[half] = l;
            }
        }
    }
    __syncthreads();

    // GEMM2 warp coords (R6 layout): wy -> m rows, wx -> n channels
    const int wy = wid & 3;
    const int wx = wid >> 2;

    float acc[2][4][4];
#pragma unroll
    for (int i = 0; i < 2; i++)
#pragma unroll
        for (int j = 0; j < 4; j++)
#pragma unroll
            for (int q = 0; q < 4; q++) acc[i][j][q] = 0.0f;

    // ldmatrix lane addressing (A2 base in u32 shared space)
    const uint32_t a2h_u = smem_u32_of(a2h);
    const uint32_t a2dlt = (uint32_t)((A2L_O - A2H_O) * 4);
    const uint32_t lds_lane_off = (uint32_t)((lane & 15) * 144 + (lane >> 4) * 16);

#pragma unroll
    for (int s = 0; s < S_; s++) {
        // ======== GEMM1: D1[w, tt*64+c] = Ae^T . xs  (M=32,N=256,K=32) ========
        // warp owns n-slice [wid*32, wid*32+32)
        {
            uint4 AH[2][2], AL[2][2];
#pragma unroll
            for (int mt = 0; mt < 2; mt++)
#pragma unroll
                for (int kt = 0; kt < 2; kt++) {
                    AH[mt][kt] = __ldg(g_Af + ((((s * 2 + mt) * 2 + kt) * 2 + 0) * 32) + lane);
                    AL[mt][kt] = __ldg(g_Af + ((((s * 2 + mt) * 2 + kt) * 2 + 1) * 32) + lane);
                }

            float d1[2][4][4];
#pragma unroll
            for (int i = 0; i < 2; i++)
#pragma unroll
                for (int j = 0; j < 4; j++)
#pragma unroll
                    for (int q = 0; q < 4; q++) d1[i][j][q] = 0.0f;

#pragma unroll
            for (int kt = 0; kt < 2; kt++) {
                const int rb = kt * 8 + (lane & 3);
#pragma unroll
                for (int nt = 0; nt < 4; nt++) {
                    const int nn = wid * 32 + nt * 8 + (lane >> 2);
                    uint32_t bh0 = xbh[rb * 264 + nn];
                    uint32_t bh1 = xbh[(rb + 4) * 264 + nn];
                    uint32_t bl0 = xbl[rb * 264 + nn];
                    uint32_t bl1 = xbl[(rb + 4) * 264 + nn];
#pragma unroll
                    for (int mt = 0; mt < 2; mt++) {
                        mma16816(d1[mt][nt], (const uint32_t*)&AH[mt][kt], bh0, bh1);
                        mma16816(d1[mt][nt], (const uint32_t*)&AL[mt][kt], bh0, bh1);
                        mma16816(d1[mt][nt], (const uint32_t*)&AH[mt][kt], bl0, bl1);
                    }
                }
            }

            // ---- pack D1 pairs (adjacent channels) into A2 [m][kw] layout ----
#pragma unroll
            for (int nt = 0; nt < 4; nt++) {
                const int n0 = wid * 32 + nt * 8 + (lane & 3) * 2;
                const int cw = (n0 & 63) >> 1;     // k-pair word index
                const int tt = n0 >> 6;
#pragma unroll
                for (int mt = 0; mt < 2; mt++) {
                    const int gm = mt * 16 + (lane >> 2);
                    const float* dd = d1[mt][nt];
                    if (gm < V_) {
                        int m2 = tt * 25 + gm;
                        uint32_t h = packbf(dd[1], dd[0]);
                        float r0 = dd[0] - __uint_as_float(h << 16);
                        float r1 = dd[1] - __uint_as_float(h & 0xffff0000u);
                        a2h[m2 * 36 + cw] = h;
                        a2l[m2 * 36 + cw] = packbf(r1, r0);
                    }
                    if (gm + 8 < V_) {
                        int m2 = tt * 25 + gm + 8;
                        uint32_t h = packbf(dd[3], dd[2]);
                        float r0 = dd[2] - __uint_as_float(h << 16);
                        float r1 = dd[3] - __uint_as_float(h & 0xffff0000u);
                        a2h[m2 * 36 + cw] = h;
                        a2l[m2 * 36 + cw] = packbf(r1, r0);
                    }
                }
            }
        }
        __syncthreads();   // A2 tiles ready

        // ======== GEMM2: acc[m][o] += xa^T . W  (M=112,N=64,K=64), 4x2 ========
        {
            const uint4* wfs = g_Wf + (s * 4) * 8 * 32 + lane;
#pragma unroll
            for (int kt = 0; kt < 4; kt++) {
                uint4 Bf[4];
#pragma unroll
                for (int j = 0; j < 4; j++)
                    Bf[j] = __ldg(wfs + (kt * 8 + wx * 4 + j) * 32);

#pragma unroll
                for (int mti = 0; mti < 2; mti++) {
                    if (!(wy == 3 && mti == 1)) {   // rows 112..127 dead
                        const uint32_t abase =
                            a2h_u + (uint32_t)((wy * 2 + mti) * 16 * 144 + kt * 32)
                            + lds_lane_off;
                        uint32_t ah[4], al[4];
                        ldsm_x4(ah, abase);
                        ldsm_x4(al, abase + a2dlt);
#pragma unroll
                        for (int j = 0; j < 4; j++) {
                            mma16816(acc[mti][j], ah, Bf[j].x, Bf[j].y);
                            mma16816(acc[mti][j], al, Bf[j].x, Bf[j].y);
                            mma16816(acc[mti][j], ah, Bf[j].z, Bf[j].w);
                        }
                    }
                }
            }
        }
        if (s < S_ - 1) __syncthreads();   // before next s overwrites A2
    }

    // -------- Epilogue: BN + residual(from gmem, L2-hot) + relu, store ------
    const int nb = wx * 32 + (lane & 3) * 2;
    float alv[8], bsv[8];
#pragma unroll
    for (int j = 0; j < 4; j++) {
        alv[2 * j]     = ab[nb + j * 8];
        alv[2 * j + 1] = ab[nb + j * 8 + 1];
        bsv[2 * j]     = ab[64 + nb + j * 8];
        bsv[2 * j + 1] = ab[64 + nb + j * 8 + 1];
    }

#pragma unroll
    for (int mti = 0; mti < 2; mti++) {
#pragma unroll
        for (int half = 0; half < 2; half++) {
            int m = (wy * 2 + mti) * 16 + (lane >> 2) + half * 8;
            if (m < COLS) {
                int tt = m / 25;
                int w  = m - tt * 25;
                int base = n * 480000 + (t0 + tt) * 25 + w;
#pragma unroll
                for (int j = 0; j < 4; j++) {
                    int o0 = nb + j * 8;
                    float c0 = acc[mti][j][half * 2];
                    float c1 = acc[mti][j][half * 2 + 1];
                    float r0 = __ldg(x + base + o0 * 7500);
                    float r1 = __ldg(x + base + (o0 + 1) * 7500);
                    float y0 = fmaf(c0, alv[2 * j], bsv[2 * j]) + r0;
                    float y1 = fmaf(c1, alv[2 * j + 1], bsv[2 * j + 1]) + r1;
                    out[base + o0 * 7500]       = fmaxf(y0, 0.0f);
                    out[base + (o0 + 1) * 7500] = fmaxf(y1, 0.0f);
                }
            }
        }
    }
}

extern "C" void kernel_launch(void* const* d_in, const int* in_sizes, int n_in,
                              void* d_out, int out_size) {
    const float* x     = (const float*)d_in[0];
    const float* A     = (const float*)d_in[1];
    const float* PA1   = (const float*)d_in[2];
    const float* PA2   = (const float*)d_in[3];
    const float* Wc    = (const float*)d_in[4];
    const float* bc    = (const float*)d_in[5];
    const float* gamma = (const float*)d_in[6];
    const float* beta  = (const float*)d_in[7];
    const float* rmean = (const float*)d_in[8];
    const float* rvar  = (const float*)d_in[9];
    float* out = (float*)d_out;

    unit_gcn_prep<<<8, 256>>>(A, PA1, PA2, Wc, bc, gamma, beta, rmean, rvar);

    cudaFuncSetAttribute(unit_gcn_main,
                         cudaFuncAttributeMaxDynamicSharedMemorySize, SMEM_BYTES);
    dim3 grid(TBLK, N_);
    unit_gcn_main<<<grid, NTHREADS, SMEM_BYTES>>>(x, out);
}